// round 7
// baseline (speedup 1.0000x reference)
#include <cuda_runtime.h>
#include <cuda_bf16.h>
#include <math.h>

#define BB 64
#define CC 512
#define KK 64
#define HW 4096
#define NSPLIT 8
#define GRP 8
#define NGROUP (BB / GRP)

#define AST 20     // A tile row stride (u32): 64 rows x 16 kpairs
#define BST 136    // B tile row stride (u32): 16 kpair-rows x 128 cols

// ---- scratch (device globals; no allocation allowed) ----
__device__ __align__(16) __nv_bfloat16 g_wb[KK * CC];
__device__ __align__(16) float         g_rnorm[BB * HW];
__device__ __align__(16) __nv_bfloat16 g_assign[(size_t)BB * KK * HW];
__device__ __align__(16) float         g_asum_part[BB * KK * 32];
__device__ __align__(16) float         g_vpart[(size_t)NSPLIT * BB * KK * CC];
__device__ __align__(16) float         g_gss[BB * KK];

__device__ __forceinline__ void mma16816(float* d, const unsigned* a, const unsigned* b) {
    asm volatile(
        "mma.sync.aligned.m16n8k16.row.col.f32.bf16.bf16.f32 "
        "{%0,%1,%2,%3}, {%4,%5,%6,%7}, {%8,%9}, {%0,%1,%2,%3};"
        : "+f"(d[0]), "+f"(d[1]), "+f"(d[2]), "+f"(d[3])
        : "r"(a[0]), "r"(a[1]), "r"(a[2]), "r"(a[3]), "r"(b[0]), "r"(b[1]));
}

__device__ __forceinline__ unsigned pack_bf2(float lo, float hi) {
    __nv_bfloat162 p = __floats2bfloat162_rn(lo, hi);
    return *reinterpret_cast<unsigned*>(&p);
}

__device__ __forceinline__ void cpasync16(unsigned* smem, const void* gmem) {
    unsigned s = (unsigned)__cvta_generic_to_shared(smem);
    asm volatile("cp.async.ca.shared.global [%0], [%1], 16;\n" :: "r"(s), "l"(gmem));
}
__device__ __forceinline__ void cp_commit() {
    asm volatile("cp.async.commit_group;\n");
}
__device__ __forceinline__ void cp_wait0() {
    asm volatile("cp.async.wait_group 0;\n");
}

// ---------------- K_pre ----------------
__global__ void k_pre(const float* __restrict__ w) {
    int t = blockIdx.x * 256 + threadIdx.x;
    if (t < KK * CC) g_wb[t] = __float2bfloat16(w[t]);
}

// ---------------- K2: norm + logits GEMM + register softmax ----------------
// grid (HW/128, GRP), 256 threads, K-chunk = 32 channels
__global__ __launch_bounds__(256) void k_logits(const float* __restrict__ x,
                                                const float* __restrict__ conv_b,
                                                int b0) {
    __shared__ __align__(16) unsigned smW[2 * KK * AST];
    __shared__ __align__(16) unsigned smX[2 * 16 * BST];
    __shared__ float rnorm_s[128];
    __shared__ float bias_s[KK];

    const int b  = b0 + blockIdx.y;
    const int bi = blockIdx.x;
    const int i0 = bi * 128;
    const int t  = threadIdx.x;
    const int lane = t & 31, warp = t >> 5;
    const int mw = warp >> 1, nw = warp & 1;
    const int g = lane >> 2, tg = lane & 3;

    if (t < KK) bias_s[t] = conv_b[t];

    const float* xb = x + (size_t)b * CC * HW + i0;
    const unsigned* wb32 = reinterpret_cast<const unsigned*>(g_wb);

    const int c4 = t & 31, cg = t >> 5;
    const int wrow = t >> 2, wq = t & 3;

    float acc[8][4];
#pragma unroll
    for (int nt = 0; nt < 8; nt++)
#pragma unroll
        for (int q = 0; q < 4; q++) acc[nt][q] = 0.f;
    float4 ssq4 = make_float4(0.f, 0.f, 0.f, 0.f);

    float4 xr[4];
    cpasync16(smW + wrow * AST + wq * 4, wb32 + wrow * (CC / 2) + wq * 4);
    cp_commit();
#pragma unroll
    for (int r = 0; r < 4; r++)
        xr[r] = *reinterpret_cast<const float4*>(xb + (size_t)(4 * cg + r) * HW + c4 * 4);
    {
        ssq4.x += xr[0].x * xr[0].x + xr[1].x * xr[1].x + xr[2].x * xr[2].x + xr[3].x * xr[3].x;
        ssq4.y += xr[0].y * xr[0].y + xr[1].y * xr[1].y + xr[2].y * xr[2].y + xr[3].y * xr[3].y;
        ssq4.z += xr[0].z * xr[0].z + xr[1].z * xr[1].z + xr[2].z * xr[2].z + xr[3].z * xr[3].z;
        ssq4.w += xr[0].w * xr[0].w + xr[1].w * xr[1].w + xr[2].w * xr[2].w + xr[3].w * xr[3].w;
        uint4 p0 = make_uint4(pack_bf2(xr[0].x, xr[1].x), pack_bf2(xr[0].y, xr[1].y),
                              pack_bf2(xr[0].z, xr[1].z), pack_bf2(xr[0].w, xr[1].w));
        uint4 p1 = make_uint4(pack_bf2(xr[2].x, xr[3].x), pack_bf2(xr[2].y, xr[3].y),
                              pack_bf2(xr[2].z, xr[3].z), pack_bf2(xr[2].w, xr[3].w));
        *reinterpret_cast<uint4*>(smX + (2 * cg) * BST + c4 * 4) = p0;
        *reinterpret_cast<uint4*>(smX + (2 * cg + 1) * BST + c4 * 4) = p1;
    }
    cp_wait0();
    __syncthreads();

    const int NIT = CC / 32;
    for (int it = 0; it < NIT; it++) {
        const int c1 = (it + 1) * 32;
        const int s = it & 1, sn = s ^ 1;
        if (it < NIT - 1) {
            cpasync16(smW + sn * (KK * AST) + wrow * AST + wq * 4,
                      wb32 + wrow * (CC / 2) + (c1 >> 1) + wq * 4);
            cp_commit();
#pragma unroll
            for (int r = 0; r < 4; r++)
                xr[r] = *reinterpret_cast<const float4*>(
                    xb + (size_t)(c1 + 4 * cg + r) * HW + c4 * 4);
        }

        const unsigned* Ws = smW + s * (KK * AST);
        const unsigned* Xs = smX + s * (16 * BST);
        const int row = mw * 16 + g;
#pragma unroll
        for (int ks = 0; ks < 2; ks++) {
            unsigned a[4];
            a[0] = Ws[row * AST + ks * 8 + tg];
            a[1] = Ws[(row + 8) * AST + ks * 8 + tg];
            a[2] = Ws[row * AST + ks * 8 + tg + 4];
            a[3] = Ws[(row + 8) * AST + ks * 8 + tg + 4];
#pragma unroll
            for (int nt = 0; nt < 8; nt++) {
                const int col = nw * 64 + nt * 8 + g;
                unsigned bf[2];
                bf[0] = Xs[(ks * 8 + tg) * BST + col];
                bf[1] = Xs[(ks * 8 + tg + 4) * BST + col];
                mma16816(acc[nt], a, bf);
            }
        }

        if (it < NIT - 1) {
            unsigned* Xn = smX + sn * (16 * BST);
            ssq4.x += xr[0].x * xr[0].x + xr[1].x * xr[1].x + xr[2].x * xr[2].x + xr[3].x * xr[3].x;
            ssq4.y += xr[0].y * xr[0].y + xr[1].y * xr[1].y + xr[2].y * xr[2].y + xr[3].y * xr[3].y;
            ssq4.z += xr[0].z * xr[0].z + xr[1].z * xr[1].z + xr[2].z * xr[2].z + xr[3].z * xr[3].z;
            ssq4.w += xr[0].w * xr[0].w + xr[1].w * xr[1].w + xr[2].w * xr[2].w + xr[3].w * xr[3].w;
            uint4 p0 = make_uint4(pack_bf2(xr[0].x, xr[1].x), pack_bf2(xr[0].y, xr[1].y),
                                  pack_bf2(xr[0].z, xr[1].z), pack_bf2(xr[0].w, xr[1].w));
            uint4 p1 = make_uint4(pack_bf2(xr[2].x, xr[3].x), pack_bf2(xr[2].y, xr[3].y),
                                  pack_bf2(xr[2].z, xr[3].z), pack_bf2(xr[2].w, xr[3].w));
            *reinterpret_cast<uint4*>(Xn + (2 * cg) * BST + c4 * 4) = p0;
            *reinterpret_cast<uint4*>(Xn + (2 * cg + 1) * BST + c4 * 4) = p1;
        }
        cp_wait0();
        __syncthreads();
    }

    // ---- ssq -> rnorm ----
    float4* ssq_sm = reinterpret_cast<float4*>(smW);
    ssq_sm[cg * 32 + c4] = ssq4;
    __syncthreads();
    if (t < 32) {
        float4 s = ssq_sm[t];
#pragma unroll
        for (int r = 1; r < 8; r++) {
            float4 u = ssq_sm[r * 32 + t];
            s.x += u.x; s.y += u.y; s.z += u.z; s.w += u.w;
        }
        float4 rn;
        rn.x = 1.f / fmaxf(sqrtf(s.x), 1e-12f);
        rn.y = 1.f / fmaxf(sqrtf(s.y), 1e-12f);
        rn.z = 1.f / fmaxf(sqrtf(s.z), 1e-12f);
        rn.w = 1.f / fmaxf(sqrtf(s.w), 1e-12f);
        reinterpret_cast<float4*>(rnorm_s)[t] = rn;
        *reinterpret_cast<float4*>(g_rnorm + (size_t)b * HW + i0 + t * 4) = rn;
    }
    __syncthreads();

    float* colmax4 = reinterpret_cast<float*>(smX);
    float* colsum4 = reinterpret_cast<float*>(smX) + 512;
    float* asum2   = reinterpret_cast<float*>(smX) + 1024;

    const int row = mw * 16 + g;
    const float b0v = bias_s[row], b1v = bias_s[row + 8];

#pragma unroll
    for (int nt = 0; nt < 8; nt++) {
        const int col = nw * 64 + nt * 8 + tg * 2;
        const float r0 = rnorm_s[col], r1 = rnorm_s[col + 1];
        acc[nt][0] = acc[nt][0] * r0 + b0v;
        acc[nt][1] = acc[nt][1] * r1 + b0v;
        acc[nt][2] = acc[nt][2] * r0 + b1v;
        acc[nt][3] = acc[nt][3] * r1 + b1v;
    }

    float mA[8], mB[8];
#pragma unroll
    for (int nt = 0; nt < 8; nt++) {
        mA[nt] = fmaxf(acc[nt][0], acc[nt][2]);
        mB[nt] = fmaxf(acc[nt][1], acc[nt][3]);
    }
#pragma unroll
    for (int off = 4; off < 32; off <<= 1) {
#pragma unroll
        for (int nt = 0; nt < 8; nt++) {
            mA[nt] = fmaxf(mA[nt], __shfl_xor_sync(0xffffffffu, mA[nt], off));
            mB[nt] = fmaxf(mB[nt], __shfl_xor_sync(0xffffffffu, mB[nt], off));
        }
    }
    if (g == 0) {
#pragma unroll
        for (int nt = 0; nt < 8; nt++) {
            const int col = nw * 64 + nt * 8 + tg * 2;
            colmax4[col * 4 + mw] = mA[nt];
            colmax4[(col + 1) * 4 + mw] = mB[nt];
        }
    }
    __syncthreads();

    float sA[8], sB[8];
#pragma unroll
    for (int nt = 0; nt < 8; nt++) {
        const int col = nw * 64 + nt * 8 + tg * 2;
        float4 c0 = *reinterpret_cast<float4*>(colmax4 + col * 4);
        float4 c1 = *reinterpret_cast<float4*>(colmax4 + (col + 1) * 4);
        float m0 = fmaxf(fmaxf(c0.x, c0.y), fmaxf(c0.z, c0.w));
        float m1 = fmaxf(fmaxf(c1.x, c1.y), fmaxf(c1.z, c1.w));
        acc[nt][0] = __expf(acc[nt][0] - m0);
        acc[nt][2] = __expf(acc[nt][2] - m0);
        acc[nt][1] = __expf(acc[nt][1] - m1);
        acc[nt][3] = __expf(acc[nt][3] - m1);
        sA[nt] = acc[nt][0] + acc[nt][2];
        sB[nt] = acc[nt][1] + acc[nt][3];
    }
#pragma unroll
    for (int off = 4; off < 32; off <<= 1) {
#pragma unroll
        for (int nt = 0; nt < 8; nt++) {
            sA[nt] += __shfl_xor_sync(0xffffffffu, sA[nt], off);
            sB[nt] += __shfl_xor_sync(0xffffffffu, sB[nt], off);
        }
    }
    if (g == 0) {
#pragma unroll
        for (int nt = 0; nt < 8; nt++) {
            const int col = nw * 64 + nt * 8 + tg * 2;
            colsum4[col * 4 + mw] = sA[nt];
            colsum4[(col + 1) * 4 + mw] = sB[nt];
        }
    }
    __syncthreads();

    unsigned* asg = reinterpret_cast<unsigned*>(g_assign) + (size_t)(b * KK) * (HW / 2);
    float rowsum = 0.f, rowsum8 = 0.f;
#pragma unroll
    for (int nt = 0; nt < 8; nt++) {
        const int col = nw * 64 + nt * 8 + tg * 2;
        float4 s0 = *reinterpret_cast<float4*>(colsum4 + col * 4);
        float4 s1 = *reinterpret_cast<float4*>(colsum4 + (col + 1) * 4);
        float inv0 = 1.f / (s0.x + s0.y + s0.z + s0.w);
        float inv1 = 1.f / (s1.x + s1.y + s1.z + s1.w);
        float a00 = acc[nt][0] * inv0, a01 = acc[nt][1] * inv1;
        float a02 = acc[nt][2] * inv0, a03 = acc[nt][3] * inv1;
        asg[(size_t)row * (HW / 2) + (i0 + col) / 2]       = pack_bf2(a00, a01);
        asg[(size_t)(row + 8) * (HW / 2) + (i0 + col) / 2] = pack_bf2(a02, a03);
        rowsum  += a00 + a01;
        rowsum8 += a02 + a03;
    }
#pragma unroll
    for (int off = 1; off < 4; off <<= 1) {
        rowsum  += __shfl_xor_sync(0xffffffffu, rowsum, off);
        rowsum8 += __shfl_xor_sync(0xffffffffu, rowsum8, off);
    }
    if (tg == 0) {
        asum2[row * 2 + nw] = rowsum;
        asum2[(row + 8) * 2 + nw] = rowsum8;
    }
    __syncthreads();
    if (t < KK)
        g_asum_part[(b * KK + t) * 32 + bi] = asum2[t * 2] + asum2[t * 2 + 1];
}

// ---------------- K3: vlad GEMM (split-K over i, i-chunk 32) ----------------
// grid (4, NSPLIT, GRP), 256 threads
__global__ __launch_bounds__(256) void k_vlad(const float* __restrict__ x, int b0) {
    __shared__ __align__(16) unsigned smA[2 * KK * AST];
    __shared__ __align__(16) unsigned smX[2 * 16 * BST];
    __shared__ __align__(16) float4 rn4[8 * 32];

    const int c2b = blockIdx.x * 128;
    const int split = blockIdx.y;
    const int b = b0 + blockIdx.z;
    const int t = threadIdx.x;
    const int lane = t & 31, warp = t >> 5;
    const int mw = warp >> 1, nw = warp & 1;
    const int g = lane >> 2, tg = lane & 3;

    {
        const int j8 = t >> 5, c4l = t & 31;
        rn4[t] = *reinterpret_cast<const float4*>(
            g_rnorm + (size_t)b * HW + j8 * 512 + c2b + c4l * 4);
    }

    const float* xb = x + (size_t)b * CC * HW;
    const unsigned* asg32 = reinterpret_cast<const unsigned*>(g_assign + (size_t)b * KK * HW);

    const int c4 = t & 31, ig = t >> 5;
    const int arow = t >> 2, aq = t & 3;

    float acc[8][4];
#pragma unroll
    for (int nt = 0; nt < 8; nt++)
#pragma unroll
        for (int q = 0; q < 4; q++) acc[nt][q] = 0.f;

    const int ibase0 = split * (HW / NSPLIT);

    float4 xr[4];
    cpasync16(smA + arow * AST + aq * 4, asg32 + arow * (HW / 2) + (ibase0 >> 1) + aq * 4);
    cp_commit();
#pragma unroll
    for (int r = 0; r < 4; r++)
        xr[r] = *reinterpret_cast<const float4*>(
            xb + (size_t)(ibase0 + 4 * ig + r) * 512 + c2b + c4 * 4);
    __syncthreads();
    {
        uint4 p0, p1;
        {
            float4 rA = rn4[((4 * ig + 0) & 7) * 32 + c4];
            float4 rB = rn4[((4 * ig + 1) & 7) * 32 + c4];
            p0 = make_uint4(pack_bf2(xr[0].x * rA.x, xr[1].x * rB.x),
                            pack_bf2(xr[0].y * rA.y, xr[1].y * rB.y),
                            pack_bf2(xr[0].z * rA.z, xr[1].z * rB.z),
                            pack_bf2(xr[0].w * rA.w, xr[1].w * rB.w));
        }
        {
            float4 rA = rn4[((4 * ig + 2) & 7) * 32 + c4];
            float4 rB = rn4[((4 * ig + 3) & 7) * 32 + c4];
            p1 = make_uint4(pack_bf2(xr[2].x * rA.x, xr[3].x * rB.x),
                            pack_bf2(xr[2].y * rA.y, xr[3].y * rB.y),
                            pack_bf2(xr[2].z * rA.z, xr[3].z * rB.z),
                            pack_bf2(xr[2].w * rA.w, xr[3].w * rB.w));
        }
        *reinterpret_cast<uint4*>(smX + (2 * ig) * BST + c4 * 4) = p0;
        *reinterpret_cast<uint4*>(smX + (2 * ig + 1) * BST + c4 * 4) = p1;
    }
    cp_wait0();
    __syncthreads();

    const int NIT = (HW / NSPLIT) / 32;
    for (int it = 0; it < NIT; it++) {
        const int ibn = ibase0 + (it + 1) * 32;
        const int s = it & 1, sn = s ^ 1;
        if (it < NIT - 1) {
            cpasync16(smA + sn * (KK * AST) + arow * AST + aq * 4,
                      asg32 + arow * (HW / 2) + (ibn >> 1) + aq * 4);
            cp_commit();
#pragma unroll
            for (int r = 0; r < 4; r++)
                xr[r] = *reinterpret_cast<const float4*>(
                    xb + (size_t)(ibn + 4 * ig + r) * 512 + c2b + c4 * 4);
        }

        const unsigned* As = smA + s * (KK * AST);
        const unsigned* Xs = smX + s * (16 * BST);
        const int row = mw * 16 + g;
#pragma unroll
        for (int ks = 0; ks < 2; ks++) {
            unsigned a[4];
            a[0] = As[row * AST + ks * 8 + tg];
            a[1] = As[(row + 8) * AST + ks * 8 + tg];
            a[2] = As[row * AST + ks * 8 + tg + 4];
            a[3] = As[(row + 8) * AST + ks * 8 + tg + 4];
#pragma unroll
            for (int nt = 0; nt < 8; nt++) {
                const int col = nw * 64 + nt * 8 + g;
                unsigned bf[2];
                bf[0] = Xs[(ks * 8 + tg) * BST + col];
                bf[1] = Xs[(ks * 8 + tg + 4) * BST + col];
                mma16816(acc[nt], a, bf);
            }
        }

        if (it < NIT - 1) {
            unsigned* Xn = smX + sn * (16 * BST);
            uint4 p0, p1;
            {
                float4 rA = rn4[((4 * ig + 0) & 7) * 32 + c4];
                float4 rB = rn4[((4 * ig + 1) & 7) * 32 + c4];
                p0 = make_uint4(pack_bf2(xr[0].x * rA.x, xr[1].x * rB.x),
                                pack_bf2(xr[0].y * rA.y, xr[1].y * rB.y),
                                pack_bf2(xr[0].z * rA.z, xr[1].z * rB.z),
                                pack_bf2(xr[0].w * rA.w, xr[1].w * rB.w));
            }
            {
                float4 rA = rn4[((4 * ig + 2) & 7) * 32 + c4];
                float4 rB = rn4[((4 * ig + 3) & 7) * 32 + c4];
                p1 = make_uint4(pack_bf2(xr[2].x * rA.x, xr[3].x * rB.x),
                                pack_bf2(xr[2].y * rA.y, xr[3].y * rB.y),
                                pack_bf2(xr[2].z * rA.z, xr[3].z * rB.z),
                                pack_bf2(xr[2].w * rA.w, xr[3].w * rB.w));
            }
            *reinterpret_cast<uint4*>(Xn + (2 * ig) * BST + c4 * 4) = p0;
            *reinterpret_cast<uint4*>(Xn + (2 * ig + 1) * BST + c4 * 4) = p1;
        }
        cp_wait0();
        __syncthreads();
    }

    float* vp = g_vpart + ((size_t)(split * BB + b)) * KK * CC;
#pragma unroll
    for (int nt = 0; nt < 8; nt++) {
        const int col = c2b + nw * 64 + nt * 8 + tg * 2;
        const int row = mw * 16 + g;
        *reinterpret_cast<float2*>(vp + (size_t)row * CC + col) =
            make_float2(acc[nt][0], acc[nt][1]);
        *reinterpret_cast<float2*>(vp + (size_t)(row + 8) * CC + col) =
            make_float2(acc[nt][2], acc[nt][3]);
    }
}

// ---------------- K4a: combine + intra-normalize ----------------
__global__ __launch_bounds__(128) void k_intra(const float* __restrict__ cent,
                                               float* __restrict__ out) {
    __shared__ float red[4];
    __shared__ float bcastA, bcastR;

    const int k = blockIdx.x, b = blockIdx.y;
    const int t = threadIdx.x;
    const int lane = t & 31, warp = t >> 5;

    if (warp == 0) {
        float s = g_asum_part[(b * KK + k) * 32 + lane];
#pragma unroll
        for (int o = 16; o > 0; o >>= 1) s += __shfl_down_sync(0xffffffffu, s, o);
        if (lane == 0) bcastA = s;
    }
    __syncthreads();
    const float as = bcastA;

    const size_t base = ((size_t)(b * KK + k)) * CC;
    const float4 cc = reinterpret_cast<const float4*>(cent + k * CC)[t];
    float4 v4 = make_float4(-as * cc.x, -as * cc.y, -as * cc.z, -as * cc.w);
#pragma unroll
    for (int s = 0; s < NSPLIT; s++) {
        const float4 a =
            reinterpret_cast<const float4*>(g_vpart + (size_t)s * BB * KK * CC + base)[t];
        v4.x += a.x; v4.y += a.y; v4.z += a.z; v4.w += a.w;
    }
    float ss = v4.x * v4.x + v4.y * v4.y + v4.z * v4.z + v4.w * v4.w;
#pragma unroll
    for (int o = 16; o > 0; o >>= 1) ss += __shfl_down_sync(0xffffffffu, ss, o);
    if (lane == 0) red[warp] = ss;
    __syncthreads();
    if (t == 0) {
        float tot = red[0] + red[1] + red[2] + red[3];
        float rinv = 1.f / fmaxf(sqrtf(tot), 1e-12f);
        bcastR = rinv;
        g_gss[b * KK + k] = tot * rinv * rinv;
    }
    __syncthreads();
    const float rinv = bcastR;
    float4 y;
    y.x = v4.x * rinv; y.y = v4.y * rinv; y.z = v4.z * rinv; y.w = v4.w * rinv;
    reinterpret_cast<float4*>(out + base)[t] = y;
}

// ---------------- K4b: global L2 normalize ----------------
__global__ __launch_bounds__(256) void k_gnorm(float* __restrict__ out) {
    __shared__ float red[8];
    __shared__ float bcast;
    const int b = blockIdx.x, t = threadIdx.x;
    const int lane = t & 31, warp = t >> 5;

    float s = (t < KK) ? g_gss[b * KK + t] : 0.f;
#pragma unroll
    for (int o = 16; o > 0; o >>= 1) s += __shfl_down_sync(0xffffffffu, s, o);
    if (lane == 0) red[warp] = s;
    __syncthreads();
    if (t == 0) {
        float tot = red[0] + red[1];
        bcast = 1.f / fmaxf(sqrtf(tot), 1e-12f);
    }
    __syncthreads();
    const float gr = bcast;
    float4* ob = reinterpret_cast<float4*>(out + (size_t)b * KK * CC);
#pragma unroll 4
    for (int u = t; u < KK * CC / 4; u += 256) {
        float4 v = ob[u];
        v.x *= gr; v.y *= gr; v.z *= gr; v.w *= gr;
        ob[u] = v;
    }
}

// ---------------- host-side stream/event plumbing (static init, pre-capture) ----
struct HxRes {
    cudaStream_t sB;
    cudaEvent_t evL[NGROUP];
    cudaEvent_t evJoin;
    HxRes() {
        cudaStreamCreateWithFlags(&sB, cudaStreamNonBlocking);
        for (int i = 0; i < NGROUP; i++)
            cudaEventCreateWithFlags(&evL[i], cudaEventDisableTiming);
        cudaEventCreateWithFlags(&evJoin, cudaEventDisableTiming);
    }
};
static HxRes hx;

// ---------------- launch ----------------
extern "C" void kernel_launch(void* const* d_in, const int* in_sizes, int n_in,
                              void* d_out, int out_size) {
    (void)in_sizes; (void)n_in; (void)out_size;
    const float* x    = (const float*)d_in[0];
    const float* w    = (const float*)d_in[1];
    const float* bias = (const float*)d_in[2];
    const float* cent = (const float*)d_in[3];
    float* out = (float*)d_out;

    k_pre<<<128, 256>>>(w);
    for (int g = 0; g < NGROUP; g++) {
        k_logits<<<dim3(HW / 128, GRP), 256>>>(x, bias, g * GRP);
        cudaEventRecord(hx.evL[g], 0);
        cudaStreamWaitEvent(hx.sB, hx.evL[g], 0);
        k_vlad<<<dim3(4, NSPLIT, GRP), 256, 0, hx.sB>>>(x, g * GRP);
    }
    cudaEventRecord(hx.evJoin, hx.sB);
    cudaStreamWaitEvent(0, hx.evJoin, 0);
    k_intra<<<dim3(KK, BB), 128>>>(cent, out);
    k_gnorm<<<BB, 256>>>(out);
}

// round 8
// speedup vs baseline: 1.0591x; 1.0591x over previous
#include <cuda_runtime.h>
#include <cuda_bf16.h>
#include <math.h>

#define BB 64
#define CC 512
#define KK 64
#define HW 4096
#define NSPLIT 4

#define AST 20     // A tile row stride (u32): 64 rows x 16 kpairs
#define BST 136    // B tile row stride (u32): 16 kpair-rows x 128 cols

#define LOG_BLKS 32                    // logits blocks per batch (HW/128)
#define VLAD_BLKS (4 * NSPLIT)         // vlad blocks per batch
#define GRP_BLKS (LOG_BLKS + VLAD_BLKS)

// ---- scratch (device globals; no allocation allowed) ----
__device__ __align__(16) __nv_bfloat16 g_wb[KK * CC];
__device__ __align__(16) float         g_rnorm[BB * HW];
__device__ __align__(16) __nv_bfloat16 g_assign[(size_t)BB * KK * HW];
__device__ __align__(16) float         g_asum_part[BB * KK * 32];
__device__ __align__(16) float         g_vpart[(size_t)NSPLIT * BB * KK * CC];
__device__ __align__(16) float         g_gss[BB * KK];
__device__ int g_flag[BB];

__device__ __forceinline__ void mma16816(float* d, const unsigned* a, const unsigned* b) {
    asm volatile(
        "mma.sync.aligned.m16n8k16.row.col.f32.bf16.bf16.f32 "
        "{%0,%1,%2,%3}, {%4,%5,%6,%7}, {%8,%9}, {%0,%1,%2,%3};"
        : "+f"(d[0]), "+f"(d[1]), "+f"(d[2]), "+f"(d[3])
        : "r"(a[0]), "r"(a[1]), "r"(a[2]), "r"(a[3]), "r"(b[0]), "r"(b[1]));
}

__device__ __forceinline__ unsigned pack_bf2(float lo, float hi) {
    __nv_bfloat162 p = __floats2bfloat162_rn(lo, hi);
    return *reinterpret_cast<unsigned*>(&p);
}

__device__ __forceinline__ void cpasync16(unsigned* smem, const void* gmem) {
    unsigned s = (unsigned)__cvta_generic_to_shared(smem);
    asm volatile("cp.async.ca.shared.global [%0], [%1], 16;\n" :: "r"(s), "l"(gmem));
}
__device__ __forceinline__ void cp_commit() {
    asm volatile("cp.async.commit_group;\n");
}
__device__ __forceinline__ void cp_wait0() {
    asm volatile("cp.async.wait_group 0;\n");
}

// ---------------- K_pre: convert weights + reset flags ----------------
__global__ void k_pre(const float* __restrict__ w) {
    int t = blockIdx.x * 256 + threadIdx.x;
    if (t < KK * CC) g_wb[t] = __float2bfloat16(w[t]);
    if (blockIdx.x == 0 && threadIdx.x < BB) g_flag[threadIdx.x] = 0;
}

// ================= logits role =================
__device__ __forceinline__ void logits_body(char* sm, const float* __restrict__ x,
                                            const float* __restrict__ conv_b,
                                            int b, int bi) {
    unsigned* smW = reinterpret_cast<unsigned*>(sm);
    unsigned* smX = reinterpret_cast<unsigned*>(sm + 10240);
    float* rnorm_s = reinterpret_cast<float*>(sm + 27648);
    float* bias_s  = reinterpret_cast<float*>(sm + 28160);

    const int i0 = bi * 128;
    const int t  = threadIdx.x;
    const int lane = t & 31, warp = t >> 5;
    const int mw = warp >> 1, nw = warp & 1;
    const int g = lane >> 2, tg = lane & 3;

    if (t < KK) bias_s[t] = conv_b[t];

    const float* xb = x + (size_t)b * CC * HW + i0;
    const unsigned* wb32 = reinterpret_cast<const unsigned*>(g_wb);

    const int c4 = t & 31, cg = t >> 5;
    const int wrow = t >> 2, wq = t & 3;

    float acc[8][4];
#pragma unroll
    for (int nt = 0; nt < 8; nt++)
#pragma unroll
        for (int q = 0; q < 4; q++) acc[nt][q] = 0.f;
    float4 ssq4 = make_float4(0.f, 0.f, 0.f, 0.f);

    float4 xr[4];
    cpasync16(smW + wrow * AST + wq * 4, wb32 + wrow * (CC / 2) + wq * 4);
    cp_commit();
#pragma unroll
    for (int r = 0; r < 4; r++)
        xr[r] = *reinterpret_cast<const float4*>(xb + (size_t)(4 * cg + r) * HW + c4 * 4);
    {
        ssq4.x += xr[0].x * xr[0].x + xr[1].x * xr[1].x + xr[2].x * xr[2].x + xr[3].x * xr[3].x;
        ssq4.y += xr[0].y * xr[0].y + xr[1].y * xr[1].y + xr[2].y * xr[2].y + xr[3].y * xr[3].y;
        ssq4.z += xr[0].z * xr[0].z + xr[1].z * xr[1].z + xr[2].z * xr[2].z + xr[3].z * xr[3].z;
        ssq4.w += xr[0].w * xr[0].w + xr[1].w * xr[1].w + xr[2].w * xr[2].w + xr[3].w * xr[3].w;
        uint4 p0 = make_uint4(pack_bf2(xr[0].x, xr[1].x), pack_bf2(xr[0].y, xr[1].y),
                              pack_bf2(xr[0].z, xr[1].z), pack_bf2(xr[0].w, xr[1].w));
        uint4 p1 = make_uint4(pack_bf2(xr[2].x, xr[3].x), pack_bf2(xr[2].y, xr[3].y),
                              pack_bf2(xr[2].z, xr[3].z), pack_bf2(xr[2].w, xr[3].w));
        *reinterpret_cast<uint4*>(smX + (2 * cg) * BST + c4 * 4) = p0;
        *reinterpret_cast<uint4*>(smX + (2 * cg + 1) * BST + c4 * 4) = p1;
    }
    cp_wait0();
    __syncthreads();

    const int NIT = CC / 32;
    for (int it = 0; it < NIT; it++) {
        const int c1 = (it + 1) * 32;
        const int s = it & 1, sn = s ^ 1;
        if (it < NIT - 1) {
            cpasync16(smW + sn * (KK * AST) + wrow * AST + wq * 4,
                      wb32 + wrow * (CC / 2) + (c1 >> 1) + wq * 4);
            cp_commit();
#pragma unroll
            for (int r = 0; r < 4; r++)
                xr[r] = *reinterpret_cast<const float4*>(
                    xb + (size_t)(c1 + 4 * cg + r) * HW + c4 * 4);
        }

        const unsigned* Ws = smW + s * (KK * AST);
        const unsigned* Xs = smX + s * (16 * BST);
        const int row = mw * 16 + g;
#pragma unroll
        for (int ks = 0; ks < 2; ks++) {
            unsigned a[4];
            a[0] = Ws[row * AST + ks * 8 + tg];
            a[1] = Ws[(row + 8) * AST + ks * 8 + tg];
            a[2] = Ws[row * AST + ks * 8 + tg + 4];
            a[3] = Ws[(row + 8) * AST + ks * 8 + tg + 4];
#pragma unroll
            for (int nt = 0; nt < 8; nt++) {
                const int col = nw * 64 + nt * 8 + g;
                unsigned bf[2];
                bf[0] = Xs[(ks * 8 + tg) * BST + col];
                bf[1] = Xs[(ks * 8 + tg + 4) * BST + col];
                mma16816(acc[nt], a, bf);
            }
        }

        if (it < NIT - 1) {
            unsigned* Xn = smX + sn * (16 * BST);
            ssq4.x += xr[0].x * xr[0].x + xr[1].x * xr[1].x + xr[2].x * xr[2].x + xr[3].x * xr[3].x;
            ssq4.y += xr[0].y * xr[0].y + xr[1].y * xr[1].y + xr[2].y * xr[2].y + xr[3].y * xr[3].y;
            ssq4.z += xr[0].z * xr[0].z + xr[1].z * xr[1].z + xr[2].z * xr[2].z + xr[3].z * xr[3].z;
            ssq4.w += xr[0].w * xr[0].w + xr[1].w * xr[1].w + xr[2].w * xr[2].w + xr[3].w * xr[3].w;
            uint4 p0 = make_uint4(pack_bf2(xr[0].x, xr[1].x), pack_bf2(xr[0].y, xr[1].y),
                                  pack_bf2(xr[0].z, xr[1].z), pack_bf2(xr[0].w, xr[1].w));
            uint4 p1 = make_uint4(pack_bf2(xr[2].x, xr[3].x), pack_bf2(xr[2].y, xr[3].y),
                                  pack_bf2(xr[2].z, xr[3].z), pack_bf2(xr[2].w, xr[3].w));
            *reinterpret_cast<uint4*>(Xn + (2 * cg) * BST + c4 * 4) = p0;
            *reinterpret_cast<uint4*>(Xn + (2 * cg + 1) * BST + c4 * 4) = p1;
        }
        cp_wait0();
        __syncthreads();
    }

    // ---- ssq -> rnorm ----
    float4* ssq_sm = reinterpret_cast<float4*>(smW);
    ssq_sm[cg * 32 + c4] = ssq4;
    __syncthreads();
    if (t < 32) {
        float4 s = ssq_sm[t];
#pragma unroll
        for (int r = 1; r < 8; r++) {
            float4 u = ssq_sm[r * 32 + t];
            s.x += u.x; s.y += u.y; s.z += u.z; s.w += u.w;
        }
        float4 rn;
        rn.x = 1.f / fmaxf(sqrtf(s.x), 1e-12f);
        rn.y = 1.f / fmaxf(sqrtf(s.y), 1e-12f);
        rn.z = 1.f / fmaxf(sqrtf(s.z), 1e-12f);
        rn.w = 1.f / fmaxf(sqrtf(s.w), 1e-12f);
        reinterpret_cast<float4*>(rnorm_s)[t] = rn;
        *reinterpret_cast<float4*>(g_rnorm + (size_t)b * HW + i0 + t * 4) = rn;
    }
    __syncthreads();

    float* colmax4 = reinterpret_cast<float*>(smX);
    float* colsum4 = reinterpret_cast<float*>(smX) + 512;
    float* asum2   = reinterpret_cast<float*>(smX) + 1024;

    const int row = mw * 16 + g;
    const float b0v = bias_s[row], b1v = bias_s[row + 8];

#pragma unroll
    for (int nt = 0; nt < 8; nt++) {
        const int col = nw * 64 + nt * 8 + tg * 2;
        const float r0 = rnorm_s[col], r1 = rnorm_s[col + 1];
        acc[nt][0] = acc[nt][0] * r0 + b0v;
        acc[nt][1] = acc[nt][1] * r1 + b0v;
        acc[nt][2] = acc[nt][2] * r0 + b1v;
        acc[nt][3] = acc[nt][3] * r1 + b1v;
    }

    float mA[8], mB[8];
#pragma unroll
    for (int nt = 0; nt < 8; nt++) {
        mA[nt] = fmaxf(acc[nt][0], acc[nt][2]);
        mB[nt] = fmaxf(acc[nt][1], acc[nt][3]);
    }
#pragma unroll
    for (int off = 4; off < 32; off <<= 1) {
#pragma unroll
        for (int nt = 0; nt < 8; nt++) {
            mA[nt] = fmaxf(mA[nt], __shfl_xor_sync(0xffffffffu, mA[nt], off));
            mB[nt] = fmaxf(mB[nt], __shfl_xor_sync(0xffffffffu, mB[nt], off));
        }
    }
    if (g == 0) {
#pragma unroll
        for (int nt = 0; nt < 8; nt++) {
            const int col = nw * 64 + nt * 8 + tg * 2;
            colmax4[col * 4 + mw] = mA[nt];
            colmax4[(col + 1) * 4 + mw] = mB[nt];
        }
    }
    __syncthreads();

    float sA[8], sB[8];
#pragma unroll
    for (int nt = 0; nt < 8; nt++) {
        const int col = nw * 64 + nt * 8 + tg * 2;
        float4 c0 = *reinterpret_cast<float4*>(colmax4 + col * 4);
        float4 c1 = *reinterpret_cast<float4*>(colmax4 + (col + 1) * 4);
        float m0 = fmaxf(fmaxf(c0.x, c0.y), fmaxf(c0.z, c0.w));
        float m1 = fmaxf(fmaxf(c1.x, c1.y), fmaxf(c1.z, c1.w));
        acc[nt][0] = __expf(acc[nt][0] - m0);
        acc[nt][2] = __expf(acc[nt][2] - m0);
        acc[nt][1] = __expf(acc[nt][1] - m1);
        acc[nt][3] = __expf(acc[nt][3] - m1);
        sA[nt] = acc[nt][0] + acc[nt][2];
        sB[nt] = acc[nt][1] + acc[nt][3];
    }
#pragma unroll
    for (int off = 4; off < 32; off <<= 1) {
#pragma unroll
        for (int nt = 0; nt < 8; nt++) {
            sA[nt] += __shfl_xor_sync(0xffffffffu, sA[nt], off);
            sB[nt] += __shfl_xor_sync(0xffffffffu, sB[nt], off);
        }
    }
    if (g == 0) {
#pragma unroll
        for (int nt = 0; nt < 8; nt++) {
            const int col = nw * 64 + nt * 8 + tg * 2;
            colsum4[col * 4 + mw] = sA[nt];
            colsum4[(col + 1) * 4 + mw] = sB[nt];
        }
    }
    __syncthreads();

    unsigned* asg = reinterpret_cast<unsigned*>(g_assign) + (size_t)(b * KK) * (HW / 2);
    float rowsum = 0.f, rowsum8 = 0.f;
#pragma unroll
    for (int nt = 0; nt < 8; nt++) {
        const int col = nw * 64 + nt * 8 + tg * 2;
        float4 s0 = *reinterpret_cast<float4*>(colsum4 + col * 4);
        float4 s1 = *reinterpret_cast<float4*>(colsum4 + (col + 1) * 4);
        float inv0 = 1.f / (s0.x + s0.y + s0.z + s0.w);
        float inv1 = 1.f / (s1.x + s1.y + s1.z + s1.w);
        float a00 = acc[nt][0] * inv0, a01 = acc[nt][1] * inv1;
        float a02 = acc[nt][2] * inv0, a03 = acc[nt][3] * inv1;
        asg[(size_t)row * (HW / 2) + (i0 + col) / 2]       = pack_bf2(a00, a01);
        asg[(size_t)(row + 8) * (HW / 2) + (i0 + col) / 2] = pack_bf2(a02, a03);
        rowsum  += a00 + a01;
        rowsum8 += a02 + a03;
    }
#pragma unroll
    for (int off = 1; off < 4; off <<= 1) {
        rowsum  += __shfl_xor_sync(0xffffffffu, rowsum, off);
        rowsum8 += __shfl_xor_sync(0xffffffffu, rowsum8, off);
    }
    if (tg == 0) {
        asum2[row * 2 + nw] = rowsum;
        asum2[(row + 8) * 2 + nw] = rowsum8;
    }
    __syncthreads();
    if (t < KK)
        g_asum_part[(b * KK + t) * 32 + bi] = asum2[t * 2] + asum2[t * 2 + 1];

    // publish: all gmem writes for this block visible, then bump flag
    __threadfence();
    __syncthreads();
    if (t == 0) atomicAdd(&g_flag[b], 1);
}

// ================= vlad role =================
__device__ __forceinline__ void vlad_body(char* sm, const float* __restrict__ x,
                                          int b, int split, int c2t) {
    unsigned* smA = reinterpret_cast<unsigned*>(sm);
    unsigned* smX = reinterpret_cast<unsigned*>(sm + 10240);
    float4* rn4   = reinterpret_cast<float4*>(sm + 27648);

    const int c2b = c2t * 128;
    const int t = threadIdx.x;
    const int lane = t & 31, warp = t >> 5;
    const int mw = warp >> 1, nw = warp & 1;
    const int g = lane >> 2, tg = lane & 3;

    // wait for this batch's logits blocks
    if (t == 0) {
        int v;
        do {
            asm volatile("ld.acquire.gpu.global.s32 %0, [%1];"
                         : "=r"(v) : "l"(g_flag + b) : "memory");
            if (v < LOG_BLKS) __nanosleep(200);
        } while (v < LOG_BLKS);
    }
    __syncthreads();

    {
        const int j8 = t >> 5, c4l = t & 31;
        rn4[t] = *reinterpret_cast<const float4*>(
            g_rnorm + (size_t)b * HW + j8 * 512 + c2b + c4l * 4);
    }

    const float* xb = x + (size_t)b * CC * HW;
    const unsigned* asg32 = reinterpret_cast<const unsigned*>(g_assign + (size_t)b * KK * HW);

    const int c4 = t & 31, ig = t >> 5;
    const int arow = t >> 2, aq = t & 3;

    float acc[8][4];
#pragma unroll
    for (int nt = 0; nt < 8; nt++)
#pragma unroll
        for (int q = 0; q < 4; q++) acc[nt][q] = 0.f;

    const int ibase0 = split * (HW / NSPLIT);

    float4 xr[4];
    cpasync16(smA + arow * AST + aq * 4, asg32 + arow * (HW / 2) + (ibase0 >> 1) + aq * 4);
    cp_commit();
#pragma unroll
    for (int r = 0; r < 4; r++)
        xr[r] = *reinterpret_cast<const float4*>(
            xb + (size_t)(ibase0 + 4 * ig + r) * 512 + c2b + c4 * 4);
    __syncthreads();
    {
        uint4 p0, p1;
        {
            float4 rA = rn4[((4 * ig + 0) & 7) * 32 + c4];
            float4 rB = rn4[((4 * ig + 1) & 7) * 32 + c4];
            p0 = make_uint4(pack_bf2(xr[0].x * rA.x, xr[1].x * rB.x),
                            pack_bf2(xr[0].y * rA.y, xr[1].y * rB.y),
                            pack_bf2(xr[0].z * rA.z, xr[1].z * rB.z),
                            pack_bf2(xr[0].w * rA.w, xr[1].w * rB.w));
        }
        {
            float4 rA = rn4[((4 * ig + 2) & 7) * 32 + c4];
            float4 rB = rn4[((4 * ig + 3) & 7) * 32 + c4];
            p1 = make_uint4(pack_bf2(xr[2].x * rA.x, xr[3].x * rB.x),
                            pack_bf2(xr[2].y * rA.y, xr[3].y * rB.y),
                            pack_bf2(xr[2].z * rA.z, xr[3].z * rB.z),
                            pack_bf2(xr[2].w * rA.w, xr[3].w * rB.w));
        }
        *reinterpret_cast<uint4*>(smX + (2 * ig) * BST + c4 * 4) = p0;
        *reinterpret_cast<uint4*>(smX + (2 * ig + 1) * BST + c4 * 4) = p1;
    }
    cp_wait0();
    __syncthreads();

    const int NIT = (HW / NSPLIT) / 32;
    for (int it = 0; it < NIT; it++) {
        const int ibn = ibase0 + (it + 1) * 32;
        const int s = it & 1, sn = s ^ 1;
        if (it < NIT - 1) {
            cpasync16(smA + sn * (KK * AST) + arow * AST + aq * 4,
                      asg32 + arow * (HW / 2) + (ibn >> 1) + aq * 4);
            cp_commit();
#pragma unroll
            for (int r = 0; r < 4; r++)
                xr[r] = *reinterpret_cast<const float4*>(
                    xb + (size_t)(ibn + 4 * ig + r) * 512 + c2b + c4 * 4);
        }

        const unsigned* As = smA + s * (KK * AST);
        const unsigned* Xs = smX + s * (16 * BST);
        const int row = mw * 16 + g;
#pragma unroll
        for (int ks = 0; ks < 2; ks++) {
            unsigned a[4];
            a[0] = As[row * AST + ks * 8 + tg];
            a[1] = As[(row + 8) * AST + ks * 8 + tg];
            a[2] = As[row * AST + ks * 8 + tg + 4];
            a[3] = As[(row + 8) * AST + ks * 8 + tg + 4];
#pragma unroll
            for (int nt = 0; nt < 8; nt++) {
                const int col = nw * 64 + nt * 8 + g;
                unsigned bf[2];
                bf[0] = Xs[(ks * 8 + tg) * BST + col];
                bf[1] = Xs[(ks * 8 + tg + 4) * BST + col];
                mma16816(acc[nt], a, bf);
            }
        }

        if (it < NIT - 1) {
            unsigned* Xn = smX + sn * (16 * BST);
            uint4 p0, p1;
            {
                float4 rA = rn4[((4 * ig + 0) & 7) * 32 + c4];
                float4 rB = rn4[((4 * ig + 1) & 7) * 32 + c4];
                p0 = make_uint4(pack_bf2(xr[0].x * rA.x, xr[1].x * rB.x),
                                pack_bf2(xr[0].y * rA.y, xr[1].y * rB.y),
                                pack_bf2(xr[0].z * rA.z, xr[1].z * rB.z),
                                pack_bf2(xr[0].w * rA.w, xr[1].w * rB.w));
            }
            {
                float4 rA = rn4[((4 * ig + 2) & 7) * 32 + c4];
                float4 rB = rn4[((4 * ig + 3) & 7) * 32 + c4];
                p1 = make_uint4(pack_bf2(xr[2].x * rA.x, xr[3].x * rB.x),
                                pack_bf2(xr[2].y * rA.y, xr[3].y * rB.y),
                                pack_bf2(xr[2].z * rA.z, xr[3].z * rB.z),
                                pack_bf2(xr[2].w * rA.w, xr[3].w * rB.w));
            }
            *reinterpret_cast<uint4*>(Xn + (2 * ig) * BST + c4 * 4) = p0;
            *reinterpret_cast<uint4*>(Xn + (2 * ig + 1) * BST + c4 * 4) = p1;
        }
        cp_wait0();
        __syncthreads();
    }

    float* vp = g_vpart + ((size_t)(split * BB + b)) * KK * CC;
#pragma unroll
    for (int nt = 0; nt < 8; nt++) {
        const int col = c2b + nw * 64 + nt * 8 + tg * 2;
        const int row = mw * 16 + g;
        *reinterpret_cast<float2*>(vp + (size_t)row * CC + col) =
            make_float2(acc[nt][0], acc[nt][1]);
        *reinterpret_cast<float2*>(vp + (size_t)(row + 8) * CC + col) =
            make_float2(acc[nt][2], acc[nt][3]);
    }
}

// ---------------- K_main: fused logits + vlad, batch-interleaved ----------------
// grid: BB * GRP_BLKS blocks, 256 threads
__global__ __launch_bounds__(256) void k_main(const float* __restrict__ x,
                                              const float* __restrict__ conv_b) {
    __shared__ __align__(16) char sm[31744];
    const int bid = blockIdx.x;
    const int b = bid / GRP_BLKS;
    const int r = bid % GRP_BLKS;
    if (r < LOG_BLKS) {
        logits_body(sm, x, conv_b, b, r);
    } else {
        const int v = r - LOG_BLKS;
        vlad_body(sm, x, b, v / 4, v % 4);
    }
}

// ---------------- K4a: combine + intra-normalize ----------------
__global__ __launch_bounds__(128) void k_intra(const float* __restrict__ cent,
                                               float* __restrict__ out) {
    __shared__ float red[4];
    __shared__ float bcastA, bcastR;

    const int k = blockIdx.x, b = blockIdx.y;
    const int t = threadIdx.x;
    const int lane = t & 31, warp = t >> 5;

    if (warp == 0) {
        float s = g_asum_part[(b * KK + k) * 32 + lane];
#pragma unroll
        for (int o = 16; o > 0; o >>= 1) s += __shfl_down_sync(0xffffffffu, s, o);
        if (lane == 0) bcastA = s;
    }
    __syncthreads();
    const float as = bcastA;

    const size_t base = ((size_t)(b * KK + k)) * CC;
    const float4 cc = reinterpret_cast<const float4*>(cent + k * CC)[t];
    float4 v4 = make_float4(-as * cc.x, -as * cc.y, -as * cc.z, -as * cc.w);
#pragma unroll
    for (int s = 0; s < NSPLIT; s++) {
        const float4 a =
            reinterpret_cast<const float4*>(g_vpart + (size_t)s * BB * KK * CC + base)[t];
        v4.x += a.x; v4.y += a.y; v4.z += a.z; v4.w += a.w;
    }
    float ss = v4.x * v4.x + v4.y * v4.y + v4.z * v4.z + v4.w * v4.w;
#pragma unroll
    for (int o = 16; o > 0; o >>= 1) ss += __shfl_down_sync(0xffffffffu, ss, o);
    if (lane == 0) red[warp] = ss;
    __syncthreads();
    if (t == 0) {
        float tot = red[0] + red[1] + red[2] + red[3];
        float rinv = 1.f / fmaxf(sqrtf(tot), 1e-12f);
        bcastR = rinv;
        g_gss[b * KK + k] = tot * rinv * rinv;
    }
    __syncthreads();
    const float rinv = bcastR;
    float4 y;
    y.x = v4.x * rinv; y.y = v4.y * rinv; y.z = v4.z * rinv; y.w = v4.w * rinv;
    reinterpret_cast<float4*>(out + base)[t] = y;
}

// ---------------- K4b: global L2 normalize ----------------
__global__ __launch_bounds__(256) void k_gnorm(float* __restrict__ out) {
    __shared__ float red[8];
    __shared__ float bcast;
    const int b = blockIdx.x, t = threadIdx.x;
    const int lane = t & 31, warp = t >> 5;

    float s = (t < KK) ? g_gss[b * KK + t] : 0.f;
#pragma unroll
    for (int o = 16; o > 0; o >>= 1) s += __shfl_down_sync(0xffffffffu, s, o);
    if (lane == 0) red[warp] = s;
    __syncthreads();
    if (t == 0) {
        float tot = red[0] + red[1];
        bcast = 1.f / fmaxf(sqrtf(tot), 1e-12f);
    }
    __syncthreads();
    const float gr = bcast;
    float4* ob = reinterpret_cast<float4*>(out + (size_t)b * KK * CC);
#pragma unroll 4
    for (int u = t; u < KK * CC / 4; u += 256) {
        float4 v = ob[u];
        v.x *= gr; v.y *= gr; v.z *= gr; v.w *= gr;
        ob[u] = v;
    }
}

// ---------------- launch ----------------
extern "C" void kernel_launch(void* const* d_in, const int* in_sizes, int n_in,
                              void* d_out, int out_size) {
    (void)in_sizes; (void)n_in; (void)out_size;
    const float* x    = (const float*)d_in[0];
    const float* w    = (const float*)d_in[1];
    const float* bias = (const float*)d_in[2];
    const float* cent = (const float*)d_in[3];
    float* out = (float*)d_out;

    k_pre<<<128, 256>>>(w);
    k_main<<<BB * GRP_BLKS, 256>>>(x, bias);
    k_intra<<<dim3(KK, BB), 128>>>(cent, out);
    k_gnorm<<<BB, 256>>>(out);
}

// round 10
// speedup vs baseline: 1.1028x; 1.0413x over previous
#include <cuda_runtime.h>
#include <cuda_bf16.h>
#include <math.h>

#define BB 64
#define CC 512
#define KK 64
#define HW 4096
#define NSPLIT 4

#define AST 20     // A tile row stride (u32): 64 rows x 16 kpairs
#define BST 136    // B tile row stride (u32): 16 kpair-rows x 128 cols

#define LOG_BLKS 32                    // logits blocks per batch
#define VLAD_BLKS (4 * NSPLIT)         // vlad blocks per batch (16)
#define PIPE_D 2                       // vlad trails logits by 2 batch groups

// ---- scratch (device globals; no allocation allowed) ----
__device__ __align__(16) __nv_bfloat16 g_wb[KK * CC];
__device__ __align__(16) float         g_rnorm[BB * HW];
__device__ __align__(16) __nv_bfloat16 g_assign[(size_t)BB * KK * HW];
__device__ __align__(16) float         g_asum_part[BB * KK * 32];
__device__ __align__(16) float         g_vpart[(size_t)NSPLIT * BB * KK * CC];
__device__ __align__(16) float         g_gss[BB * KK];
__device__ int g_flag[BB];

__device__ __forceinline__ void mma16816(float* d, const unsigned* a, const unsigned* b) {
    asm volatile(
        "mma.sync.aligned.m16n8k16.row.col.f32.bf16.bf16.f32 "
        "{%0,%1,%2,%3}, {%4,%5,%6,%7}, {%8,%9}, {%0,%1,%2,%3};"
        : "+f"(d[0]), "+f"(d[1]), "+f"(d[2]), "+f"(d[3])
        : "r"(a[0]), "r"(a[1]), "r"(a[2]), "r"(a[3]), "r"(b[0]), "r"(b[1]));
}

__device__ __forceinline__ unsigned pack_bf2(float lo, float hi) {
    __nv_bfloat162 p = __floats2bfloat162_rn(lo, hi);
    return *reinterpret_cast<unsigned*>(&p);
}

__device__ __forceinline__ void cpasync16(unsigned* smem, const void* gmem) {
    unsigned s = (unsigned)__cvta_generic_to_shared(smem);
    asm volatile("cp.async.ca.shared.global [%0], [%1], 16;\n" :: "r"(s), "l"(gmem));
}
__device__ __forceinline__ void cp_commit() {
    asm volatile("cp.async.commit_group;\n");
}
__device__ __forceinline__ void cp_wait0() {
    asm volatile("cp.async.wait_group 0;\n");
}

// ---------------- K_pre: convert weights + reset flags ----------------
__global__ void k_pre(const float* __restrict__ w) {
    int t = blockIdx.x * 256 + threadIdx.x;
    if (t < KK * CC) g_wb[t] = __float2bfloat16(w[t]);
    if (blockIdx.x == 0 && threadIdx.x < BB) g_flag[threadIdx.x] = 0;
}

// ================= logits role =================
__device__ __forceinline__ void logits_body(char* sm, const float* __restrict__ x,
                                            const float* __restrict__ conv_b,
                                            int b, int bi) {
    unsigned* smW = reinterpret_cast<unsigned*>(sm);
    unsigned* smX = reinterpret_cast<unsigned*>(sm + 10240);
    float* rnorm_s = reinterpret_cast<float*>(sm + 27648);
    float* bias_s  = reinterpret_cast<float*>(sm + 28160);

    const int i0 = bi * 128;
    const int t  = threadIdx.x;
    const int lane = t & 31, warp = t >> 5;
    const int mw = warp >> 1, nw = warp & 1;
    const int g = lane >> 2, tg = lane & 3;

    if (t < KK) bias_s[t] = conv_b[t];

    const float* xb = x + (size_t)b * CC * HW + i0;
    const unsigned* wb32 = reinterpret_cast<const unsigned*>(g_wb);

    const int c4 = t & 31, cg = t >> 5;
    const int wrow = t >> 2, wq = t & 3;

    float acc[8][4];
#pragma unroll
    for (int nt = 0; nt < 8; nt++)
#pragma unroll
        for (int q = 0; q < 4; q++) acc[nt][q] = 0.f;
    float4 ssq4 = make_float4(0.f, 0.f, 0.f, 0.f);

    float4 xr[4];
    cpasync16(smW + wrow * AST + wq * 4, wb32 + wrow * (CC / 2) + wq * 4);
    cp_commit();
#pragma unroll
    for (int r = 0; r < 4; r++)
        xr[r] = *reinterpret_cast<const float4*>(xb + (size_t)(4 * cg + r) * HW + c4 * 4);
    {
        ssq4.x += xr[0].x * xr[0].x + xr[1].x * xr[1].x + xr[2].x * xr[2].x + xr[3].x * xr[3].x;
        ssq4.y += xr[0].y * xr[0].y + xr[1].y * xr[1].y + xr[2].y * xr[2].y + xr[3].y * xr[3].y;
        ssq4.z += xr[0].z * xr[0].z + xr[1].z * xr[1].z + xr[2].z * xr[2].z + xr[3].z * xr[3].z;
        ssq4.w += xr[0].w * xr[0].w + xr[1].w * xr[1].w + xr[2].w * xr[2].w + xr[3].w * xr[3].w;
        uint4 p0 = make_uint4(pack_bf2(xr[0].x, xr[1].x), pack_bf2(xr[0].y, xr[1].y),
                              pack_bf2(xr[0].z, xr[1].z), pack_bf2(xr[0].w, xr[1].w));
        uint4 p1 = make_uint4(pack_bf2(xr[2].x, xr[3].x), pack_bf2(xr[2].y, xr[3].y),
                              pack_bf2(xr[2].z, xr[3].z), pack_bf2(xr[2].w, xr[3].w));
        *reinterpret_cast<uint4*>(smX + (2 * cg) * BST + c4 * 4) = p0;
        *reinterpret_cast<uint4*>(smX + (2 * cg + 1) * BST + c4 * 4) = p1;
    }
    cp_wait0();
    __syncthreads();

    const int NIT = CC / 32;
    for (int it = 0; it < NIT; it++) {
        const int c1 = (it + 1) * 32;
        const int s = it & 1, sn = s ^ 1;
        if (it < NIT - 1) {
            cpasync16(smW + sn * (KK * AST) + wrow * AST + wq * 4,
                      wb32 + wrow * (CC / 2) + (c1 >> 1) + wq * 4);
            cp_commit();
#pragma unroll
            for (int r = 0; r < 4; r++)
                xr[r] = *reinterpret_cast<const float4*>(
                    xb + (size_t)(c1 + 4 * cg + r) * HW + c4 * 4);
        }

        const unsigned* Ws = smW + s * (KK * AST);
        const unsigned* Xs = smX + s * (16 * BST);
        const int row = mw * 16 + g;
#pragma unroll
        for (int ks = 0; ks < 2; ks++) {
            unsigned a[4];
            a[0] = Ws[row * AST + ks * 8 + tg];
            a[1] = Ws[(row + 8) * AST + ks * 8 + tg];
            a[2] = Ws[row * AST + ks * 8 + tg + 4];
            a[3] = Ws[(row + 8) * AST + ks * 8 + tg + 4];
#pragma unroll
            for (int nt = 0; nt < 8; nt++) {
                const int col = nw * 64 + nt * 8 + g;
                unsigned bf[2];
                bf[0] = Xs[(ks * 8 + tg) * BST + col];
                bf[1] = Xs[(ks * 8 + tg + 4) * BST + col];
                mma16816(acc[nt], a, bf);
            }
        }

        if (it < NIT - 1) {
            unsigned* Xn = smX + sn * (16 * BST);
            ssq4.x += xr[0].x * xr[0].x + xr[1].x * xr[1].x + xr[2].x * xr[2].x + xr[3].x * xr[3].x;
            ssq4.y += xr[0].y * xr[0].y + xr[1].y * xr[1].y + xr[2].y * xr[2].y + xr[3].y * xr[3].y;
            ssq4.z += xr[0].z * xr[0].z + xr[1].z * xr[1].z + xr[2].z * xr[2].z + xr[3].z * xr[3].z;
            ssq4.w += xr[0].w * xr[0].w + xr[1].w * xr[1].w + xr[2].w * xr[2].w + xr[3].w * xr[3].w;
            uint4 p0 = make_uint4(pack_bf2(xr[0].x, xr[1].x), pack_bf2(xr[0].y, xr[1].y),
                                  pack_bf2(xr[0].z, xr[1].z), pack_bf2(xr[0].w, xr[1].w));
            uint4 p1 = make_uint4(pack_bf2(xr[2].x, xr[3].x), pack_bf2(xr[2].y, xr[3].y),
                                  pack_bf2(xr[2].z, xr[3].z), pack_bf2(xr[2].w, xr[3].w));
            *reinterpret_cast<uint4*>(Xn + (2 * cg) * BST + c4 * 4) = p0;
            *reinterpret_cast<uint4*>(Xn + (2 * cg + 1) * BST + c4 * 4) = p1;
        }
        cp_wait0();
        __syncthreads();
    }

    // ---- ssq -> rnorm ----
    float4* ssq_sm = reinterpret_cast<float4*>(smW);
    ssq_sm[cg * 32 + c4] = ssq4;
    __syncthreads();
    if (t < 32) {
        float4 s = ssq_sm[t];
#pragma unroll
        for (int r = 1; r < 8; r++) {
            float4 u = ssq_sm[r * 32 + t];
            s.x += u.x; s.y += u.y; s.z += u.z; s.w += u.w;
        }
        float4 rn;
        rn.x = 1.f / fmaxf(sqrtf(s.x), 1e-12f);
        rn.y = 1.f / fmaxf(sqrtf(s.y), 1e-12f);
        rn.z = 1.f / fmaxf(sqrtf(s.z), 1e-12f);
        rn.w = 1.f / fmaxf(sqrtf(s.w), 1e-12f);
        reinterpret_cast<float4*>(rnorm_s)[t] = rn;
        *reinterpret_cast<float4*>(g_rnorm + (size_t)b * HW + i0 + t * 4) = rn;
    }
    __syncthreads();

    float* colmax4 = reinterpret_cast<float*>(smX);
    float* colsum4 = reinterpret_cast<float*>(smX) + 512;
    float* asum2   = reinterpret_cast<float*>(smX) + 1024;

    const int row = mw * 16 + g;
    const float b0v = bias_s[row], b1v = bias_s[row + 8];

#pragma unroll
    for (int nt = 0; nt < 8; nt++) {
        const int col = nw * 64 + nt * 8 + tg * 2;
        const float r0 = rnorm_s[col], r1 = rnorm_s[col + 1];
        acc[nt][0] = acc[nt][0] * r0 + b0v;
        acc[nt][1] = acc[nt][1] * r1 + b0v;
        acc[nt][2] = acc[nt][2] * r0 + b1v;
        acc[nt][3] = acc[nt][3] * r1 + b1v;
    }

    float mA[8], mB[8];
#pragma unroll
    for (int nt = 0; nt < 8; nt++) {
        mA[nt] = fmaxf(acc[nt][0], acc[nt][2]);
        mB[nt] = fmaxf(acc[nt][1], acc[nt][3]);
    }
#pragma unroll
    for (int off = 4; off < 32; off <<= 1) {
#pragma unroll
        for (int nt = 0; nt < 8; nt++) {
            mA[nt] = fmaxf(mA[nt], __shfl_xor_sync(0xffffffffu, mA[nt], off));
            mB[nt] = fmaxf(mB[nt], __shfl_xor_sync(0xffffffffu, mB[nt], off));
        }
    }
    if (g == 0) {
#pragma unroll
        for (int nt = 0; nt < 8; nt++) {
            const int col = nw * 64 + nt * 8 + tg * 2;
            colmax4[col * 4 + mw] = mA[nt];
            colmax4[(col + 1) * 4 + mw] = mB[nt];
        }
    }
    __syncthreads();

    float sA[8], sB[8];
#pragma unroll
    for (int nt = 0; nt < 8; nt++) {
        const int col = nw * 64 + nt * 8 + tg * 2;
        float4 c0 = *reinterpret_cast<float4*>(colmax4 + col * 4);
        float4 c1 = *reinterpret_cast<float4*>(colmax4 + (col + 1) * 4);
        float m0 = fmaxf(fmaxf(c0.x, c0.y), fmaxf(c0.z, c0.w));
        float m1 = fmaxf(fmaxf(c1.x, c1.y), fmaxf(c1.z, c1.w));
        acc[nt][0] = __expf(acc[nt][0] - m0);
        acc[nt][2] = __expf(acc[nt][2] - m0);
        acc[nt][1] = __expf(acc[nt][1] - m1);
        acc[nt][3] = __expf(acc[nt][3] - m1);
        sA[nt] = acc[nt][0] + acc[nt][2];
        sB[nt] = acc[nt][1] + acc[nt][3];
    }
#pragma unroll
    for (int off = 4; off < 32; off <<= 1) {
#pragma unroll
        for (int nt = 0; nt < 8; nt++) {
            sA[nt] += __shfl_xor_sync(0xffffffffu, sA[nt], off);
            sB[nt] += __shfl_xor_sync(0xffffffffu, sB[nt], off);
        }
    }
    if (g == 0) {
#pragma unroll
        for (int nt = 0; nt < 8; nt++) {
            const int col = nw * 64 + nt * 8 + tg * 2;
            colsum4[col * 4 + mw] = sA[nt];
            colsum4[(col + 1) * 4 + mw] = sB[nt];
        }
    }
    __syncthreads();

    unsigned* asg = reinterpret_cast<unsigned*>(g_assign) + (size_t)(b * KK) * (HW / 2);
    float rowsum = 0.f, rowsum8 = 0.f;
#pragma unroll
    for (int nt = 0; nt < 8; nt++) {
        const int col = nw * 64 + nt * 8 + tg * 2;
        float4 s0 = *reinterpret_cast<float4*>(colsum4 + col * 4);
        float4 s1 = *reinterpret_cast<float4*>(colsum4 + (col + 1) * 4);
        float inv0 = 1.f / (s0.x + s0.y + s0.z + s0.w);
        float inv1 = 1.f / (s1.x + s1.y + s1.z + s1.w);
        float a00 = acc[nt][0] * inv0, a01 = acc[nt][1] * inv1;
        float a02 = acc[nt][2] * inv0, a03 = acc[nt][3] * inv1;
        asg[(size_t)row * (HW / 2) + (i0 + col) / 2]       = pack_bf2(a00, a01);
        asg[(size_t)(row + 8) * (HW / 2) + (i0 + col) / 2] = pack_bf2(a02, a03);
        rowsum  += a00 + a01;
        rowsum8 += a02 + a03;
    }
#pragma unroll
    for (int off = 1; off < 4; off <<= 1) {
        rowsum  += __shfl_xor_sync(0xffffffffu, rowsum, off);
        rowsum8 += __shfl_xor_sync(0xffffffffu, rowsum8, off);
    }
    if (tg == 0) {
        asum2[row * 2 + nw] = rowsum;
        asum2[(row + 8) * 2 + nw] = rowsum8;
    }
    __syncthreads();
    if (t < KK)
        g_asum_part[(b * KK + t) * 32 + bi] = asum2[t * 2] + asum2[t * 2 + 1];

    // publish
    __threadfence();
    __syncthreads();
    if (t == 0) atomicAdd(&g_flag[b], 1);
}

// ================= vlad role =================
__device__ __forceinline__ void vlad_body(char* sm, const float* __restrict__ x,
                                          int b, int split, int c2t) {
    unsigned* smA = reinterpret_cast<unsigned*>(sm);
    unsigned* smX = reinterpret_cast<unsigned*>(sm + 10240);
    float4* rn4   = reinterpret_cast<float4*>(sm + 27648);

    const int c2b = c2t * 128;
    const int t = threadIdx.x;
    const int lane = t & 31, warp = t >> 5;
    const int mw = warp >> 1, nw = warp & 1;
    const int g = lane >> 2, tg = lane & 3;

    // wait for this batch's logits blocks (should be already done with PIPE_D lag)
    if (t == 0) {
        int v;
        do {
            asm volatile("ld.acquire.gpu.global.s32 %0, [%1];"
                         : "=r"(v) : "l"(g_flag + b) : "memory");
            if (v < LOG_BLKS) __nanosleep(200);
        } while (v < LOG_BLKS);
    }
    __syncthreads();

    {
        const int j8 = t >> 5, c4l = t & 31;
        rn4[t] = *reinterpret_cast<const float4*>(
            g_rnorm + (size_t)b * HW + j8 * 512 + c2b + c4l * 4);
    }

    const float* xb = x + (size_t)b * CC * HW;
    const unsigned* asg32 = reinterpret_cast<const unsigned*>(g_assign + (size_t)b * KK * HW);

    const int c4 = t & 31, ig = t >> 5;
    const int arow = t >> 2, aq = t & 3;

    float acc[8][4];
#pragma unroll
    for (int nt = 0; nt < 8; nt++)
#pragma unroll
        for (int q = 0; q < 4; q++) acc[nt][q] = 0.f;

    const int ibase0 = split * (HW / NSPLIT);

    float4 xr[4];
    cpasync16(smA + arow * AST + aq * 4, asg32 + arow * (HW / 2) + (ibase0 >> 1) + aq * 4);
    cp_commit();
#pragma unroll
    for (int r = 0; r < 4; r++)
        xr[r] = *reinterpret_cast<const float4*>(
            xb + (size_t)(ibase0 + 4 * ig + r) * 512 + c2b + c4 * 4);
    __syncthreads();
    {
        uint4 p0, p1;
        {
            float4 rA = rn4[((4 * ig + 0) & 7) * 32 + c4];
            float4 rB = rn4[((4 * ig + 1) & 7) * 32 + c4];
            p0 = make_uint4(pack_bf2(xr[0].x * rA.x, xr[1].x * rB.x),
                            pack_bf2(xr[0].y * rA.y, xr[1].y * rB.y),
                            pack_bf2(xr[0].z * rA.z, xr[1].z * rB.z),
                            pack_bf2(xr[0].w * rA.w, xr[1].w * rB.w));
        }
        {
            float4 rA = rn4[((4 * ig + 2) & 7) * 32 + c4];
            float4 rB = rn4[((4 * ig + 3) & 7) * 32 + c4];
            p1 = make_uint4(pack_bf2(xr[2].x * rA.x, xr[3].x * rB.x),
                            pack_bf2(xr[2].y * rA.y, xr[3].y * rB.y),
                            pack_bf2(xr[2].z * rA.z, xr[3].z * rB.z),
                            pack_bf2(xr[2].w * rA.w, xr[3].w * rB.w));
        }
        *reinterpret_cast<uint4*>(smX + (2 * ig) * BST + c4 * 4) = p0;
        *reinterpret_cast<uint4*>(smX + (2 * ig + 1) * BST + c4 * 4) = p1;
    }
    cp_wait0();
    __syncthreads();

    const int NIT = (HW / NSPLIT) / 32;
    for (int it = 0; it < NIT; it++) {
        const int ibn = ibase0 + (it + 1) * 32;
        const int s = it & 1, sn = s ^ 1;
        if (it < NIT - 1) {
            cpasync16(smA + sn * (KK * AST) + arow * AST + aq * 4,
                      asg32 + arow * (HW / 2) + (ibn >> 1) + aq * 4);
            cp_commit();
#pragma unroll
            for (int r = 0; r < 4; r++)
                xr[r] = *reinterpret_cast<const float4*>(
                    xb + (size_t)(ibn + 4 * ig + r) * 512 + c2b + c4 * 4);
        }

        const unsigned* As = smA + s * (KK * AST);
        const unsigned* Xs = smX + s * (16 * BST);
        const int row = mw * 16 + g;
#pragma unroll
        for (int ks = 0; ks < 2; ks++) {
            unsigned a[4];
            a[0] = As[row * AST + ks * 8 + tg];
            a[1] = As[(row + 8) * AST + ks * 8 + tg];
            a[2] = As[row * AST + ks * 8 + tg + 4];
            a[3] = As[(row + 8) * AST + ks * 8 + tg + 4];
#pragma unroll
            for (int nt = 0; nt < 8; nt++) {
                const int col = nw * 64 + nt * 8 + g;
                unsigned bf[2];
                bf[0] = Xs[(ks * 8 + tg) * BST + col];
                bf[1] = Xs[(ks * 8 + tg + 4) * BST + col];
                mma16816(acc[nt], a, bf);
            }
        }

        if (it < NIT - 1) {
            unsigned* Xn = smX + sn * (16 * BST);
            uint4 p0, p1;
            {
                float4 rA = rn4[((4 * ig + 0) & 7) * 32 + c4];
                float4 rB = rn4[((4 * ig + 1) & 7) * 32 + c4];
                p0 = make_uint4(pack_bf2(xr[0].x * rA.x, xr[1].x * rB.x),
                                pack_bf2(xr[0].y * rA.y, xr[1].y * rB.y),
                                pack_bf2(xr[0].z * rA.z, xr[1].z * rB.z),
                                pack_bf2(xr[0].w * rA.w, xr[1].w * rB.w));
            }
            {
                float4 rA = rn4[((4 * ig + 2) & 7) * 32 + c4];
                float4 rB = rn4[((4 * ig + 3) & 7) * 32 + c4];
                p1 = make_uint4(pack_bf2(xr[2].x * rA.x, xr[3].x * rB.x),
                                pack_bf2(xr[2].y * rA.y, xr[3].y * rB.y),
                                pack_bf2(xr[2].z * rA.z, xr[3].z * rB.z),
                                pack_bf2(xr[2].w * rA.w, xr[3].w * rB.w));
            }
            *reinterpret_cast<uint4*>(Xn + (2 * ig) * BST + c4 * 4) = p0;
            *reinterpret_cast<uint4*>(Xn + (2 * ig + 1) * BST + c4 * 4) = p1;
        }
        cp_wait0();
        __syncthreads();
    }

    float* vp = g_vpart + ((size_t)(split * BB + b)) * KK * CC;
#pragma unroll
    for (int nt = 0; nt < 8; nt++) {
        const int col = c2b + nw * 64 + nt * 8 + tg * 2;
        const int row = mw * 16 + g;
        *reinterpret_cast<float2*>(vp + (size_t)row * CC + col) =
            make_float2(acc[nt][0], acc[nt][1]);
        *reinterpret_cast<float2*>(vp + (size_t)(row + 8) * CC + col) =
            make_float2(acc[nt][2], acc[nt][3]);
    }
}

// ---------------- K_main: fused, software-pipelined block order ----------------
// bid order: L0, L1, [L2 V0], [L3 V1], ..., [L63 V61], V62, V63
__global__ __launch_bounds__(256) void k_main(const float* __restrict__ x,
                                              const float* __restrict__ conv_b) {
    __shared__ __align__(16) char sm[31744];
    const int bid = blockIdx.x;

    const int head = PIPE_D * LOG_BLKS;                    // pure-L prefix
    const int pairN = (BB - PIPE_D);                       // paired slots
    const int pairSz = LOG_BLKS + VLAD_BLKS;               // 48

    int roleL, b, sub;
    if (bid < head) {
        roleL = 1; b = bid / LOG_BLKS; sub = bid % LOG_BLKS;
    } else {
        int q = bid - head;
        if (q < pairN * pairSz) {
            int pair = q / pairSz, r = q % pairSz;
            if (r < LOG_BLKS) { roleL = 1; b = PIPE_D + pair; sub = r; }
            else              { roleL = 0; b = pair;          sub = r - LOG_BLKS; }
        } else {
            int q2 = q - pairN * pairSz;
            roleL = 0; b = pairN + q2 / VLAD_BLKS; sub = q2 % VLAD_BLKS;
        }
    }

    if (roleL) logits_body(sm, x, conv_b, b, sub);
    else       vlad_body(sm, x, b, sub / 4, sub % 4);
}

// ---------------- K4a: combine + intra-normalize ----------------
__global__ __launch_bounds__(128) void k_intra(const float* __restrict__ cent,
                                               float* __restrict__ out) {
    __shared__ float red[4];
    __shared__ float bcastA, bcastR;

    const int k = blockIdx.x, b = blockIdx.y;
    const int t = threadIdx.x;
    const int lane = t & 31, warp = t >> 5;

    if (warp == 0) {
        float s = g_asum_part[(b * KK + k) * 32 + lane];
#pragma unroll
        for (int o = 16; o > 0; o >>= 1) s += __shfl_down_sync(0xffffffffu, s, o);
        if (lane == 0) bcastA = s;
    }
    __syncthreads();
    const float as = bcastA;

    const size_t base = ((size_t)(b * KK + k)) * CC;
    const float4 cc = reinterpret_cast<const float4*>(cent + k * CC)[t];
    float4 v4 = make_float4(-as * cc.x, -as * cc.y, -as * cc.z, -as * cc.w);
#pragma unroll
    for (int s = 0; s < NSPLIT; s++) {
        const float4 a =
            reinterpret_cast<const float4*>(g_vpart + (size_t)s * BB * KK * CC + base)[t];
        v4.x += a.x; v4.y += a.y; v4.z += a.z; v4.w += a.w;
    }
    float ss = v4.x * v4.x + v4.y * v4.y + v4.z * v4.z + v4.w * v4.w;
#pragma unroll
    for (int o = 16; o > 0; o >>= 1) ss += __shfl_down_sync(0xffffffffu, ss, o);
    if (lane == 0) red[warp] = ss;
    __syncthreads();
    if (t == 0) {
        float tot = red[0] + red[1] + red[2] + red[3];
        float rinv = 1.f / fmaxf(sqrtf(tot), 1e-12f);
        bcastR = rinv;
        g_gss[b * KK + k] = tot * rinv * rinv;
    }
    __syncthreads();
    const float rinv = bcastR;
    float4 y;
    y.x = v4.x * rinv; y.y = v4.y * rinv; y.z = v4.z * rinv; y.w = v4.w * rinv;
    reinterpret_cast<float4*>(out + base)[t] = y;
}

// ---------------- K4b: global L2 normalize ----------------
__global__ __launch_bounds__(256) void k_gnorm(float* __restrict__ out) {
    __shared__ float red[8];
    __shared__ float bcast;
    const int b = blockIdx.x, t = threadIdx.x;
    const int lane = t & 31, warp = t >> 5;

    float s = (t < KK) ? g_gss[b * KK + t] : 0.f;
#pragma unroll
    for (int o = 16; o > 0; o >>= 1) s += __shfl_down_sync(0xffffffffu, s, o);
    if (lane == 0) red[warp] = s;
    __syncthreads();
    if (t == 0) {
        float tot = red[0] + red[1];
        bcast = 1.f / fmaxf(sqrtf(tot), 1e-12f);
    }
    __syncthreads();
    const float gr = bcast;
    float4* ob = reinterpret_cast<float4*>(out + (size_t)b * KK * CC);
#pragma unroll 4
    for (int u = t; u < KK * CC / 4; u += 256) {
        float4 v = ob[u];
        v.x *= gr; v.y *= gr; v.z *= gr; v.w *= gr;
        ob[u] = v;
    }
}

// ---------------- launch ----------------
extern "C" void kernel_launch(void* const* d_in, const int* in_sizes, int n_in,
                              void* d_out, int out_size) {
    (void)in_sizes; (void)n_in; (void)out_size;
    const float* x    = (const float*)d_in[0];
    const float* w    = (const float*)d_in[1];
    const float* bias = (const float*)d_in[2];
    const float* cent = (const float*)d_in[3];
    float* out = (float*)d_out;

    k_pre<<<128, 256>>>(w);
    k_main<<<BB * (LOG_BLKS + VLAD_BLKS), 256>>>(x, bias);
    k_intra<<<dim3(KK, BB), 128>>>(cent, out);
    k_gnorm<<<BB, 256>>>(out);
}